// round 13
// baseline (speedup 1.0000x reference)
#include <cuda_runtime.h>
#include <cuda_fp16.h>
#include <math.h>
#include <stdint.h>

#define B_DIM 4096
#define IN_DIM 1024
#define H_DIM 2048
#define A_DIM 64
#define A2_DIM 4096

// ---------------- scratch (__device__ globals; no allocs allowed) ----------
// GEMM operands stored as fp16 pairs (uint32 = half2), k-PERMUTED:
// within each 32-k block, element k lives at pos = 8*((k&7)>>1) + 2*(k>>3) + (k&1).
__device__ uint32_t g_inc [B_DIM * IN_DIM / 2];
__device__ uint32_t g_hinc[B_DIM * H_DIM / 2];
__device__ uint32_t g_W1c [H_DIM * IN_DIM / 2];
__device__ uint32_t g_Wihc[3 * H_DIM * H_DIM / 2];
__device__ uint32_t g_Whhc[3 * H_DIM * H_DIM / 2];
__device__ uint32_t g_W2c [A2_DIM * H_DIM / 2];
__device__ uint32_t g_x   [B_DIM * H_DIM / 2];      // fc1 out (relu, fp16, perm)
__device__ float    g_gi  [B_DIM * 3 * H_DIM];      // fp32 plain
__device__ float    g_gh  [B_DIM * 3 * H_DIM];      // fp32 plain
__device__ uint32_t g_hc  [B_DIM * H_DIM / 2];      // new hidden (fp16, perm)
__device__ float    g_q   [B_DIM * A2_DIM];         // fp32 plain

// ---------------- helpers --------------------------------------------------
__device__ __forceinline__ uint32_t smem_u32(const void* p) {
    uint32_t a;
    asm("{ .reg .u64 t; cvta.to.shared.u64 t, %1; cvt.u32.u64 %0, t; }"
        : "=r"(a) : "l"(p));
    return a;
}
__device__ __forceinline__ uint32_t h2u(float a, float b) {
    __half2 h = __floats2half2_rn(a, b);     // low = a (even k), high = b
    return *reinterpret_cast<uint32_t*>(&h);
}
__device__ __forceinline__ void cp_async16(uint32_t dst, const void* src) {
    asm volatile("cp.async.cg.shared.global [%0], [%1], 16;" :: "r"(dst), "l"(src));
}
__device__ __forceinline__ void mma_f16(float* c,
                                        uint32_t a0, uint32_t a1, uint32_t a2, uint32_t a3,
                                        uint32_t b0, uint32_t b1) {
    asm volatile(
        "mma.sync.aligned.m16n8k16.row.col.f32.f16.f16.f32 "
        "{%0,%1,%2,%3}, {%4,%5,%6,%7}, {%8,%9}, {%0,%1,%2,%3};"
        : "+f"(c[0]), "+f"(c[1]), "+f"(c[2]), "+f"(c[3])
        : "r"(a0), "r"(a1), "r"(a2), "r"(a3), "r"(b0), "r"(b1));
}
// uint32 index (within a row of N/2 uint32) of the half2 holding (k, k+1), k even
__device__ __forceinline__ int hperm_u32(int k) {
    return (k >> 5) * 16 + ((k & 7) >> 1) * 4 + ((k & 31) >> 3);
}

// ---------------- fp16 mma.sync GEMM ---------------------------------------
// C[M,N] = A[M,K] @ Bw[N,K]^T + bias. CTA 128x128, BK=32, 256 thr, occ 2,
// 3-stage cp.async ring, one barrier per chunk. blockIdx.z selects between
// two independent problems (used to merge the gi / gh GEMMs into one launch).
#define ATILE_B 8192                      // 128 rows x 64 B
#define STAGE_B (2 * ATILE_B)             // A + B
#define NSTG 3
#define SMEM_BYTES (NSTG * STAGE_B)       // 49152 B

template<int MODE>   // 0: fp32 plain store; 1: relu + fp16 PERMUTED store
__global__ __launch_bounds__(256, 2)
void gemm_f16k(const uint32_t* __restrict__ A0, const uint32_t* __restrict__ Bw0,
               const float* __restrict__ bias0, void* __restrict__ C0,
               const uint32_t* __restrict__ A1, const uint32_t* __restrict__ Bw1,
               const float* __restrict__ bias1, void* __restrict__ C1,
               int K, int N) {
    extern __shared__ uint32_t sm[];
    const uint32_t* A    = blockIdx.z ? A1    : A0;
    const uint32_t* Bw   = blockIdx.z ? Bw1   : Bw0;
    const float*    bias = blockIdx.z ? bias1 : bias0;
    void*           Cout = blockIdx.z ? C1    : C0;

    const int tid  = threadIdx.x;
    const int bm   = blockIdx.y * 128;
    const int bn   = blockIdx.x * 128;
    const int warp = tid >> 5, lane = tid & 31;
    const int wm   = (warp & 3) * 32;
    const int wn   = (warp >> 2) * 64;
    const int g    = lane >> 2;           // row-in-8 group
    const int t    = lane & 3;            // k phase
    const int NC   = K >> 5;              // K chunks of 32
    const int KW   = K >> 1;              // uint32 per operand row

    const uint32_t sb = smem_u32(sm);
    const int lrow = tid >> 2;            // loader row 0..63 (+64)
    const int ltb  = tid & 3;             // 16B block within 64B row-chunk

    float acc[2][8][4];
    #pragma unroll
    for (int mt = 0; mt < 2; mt++)
        #pragma unroll
        for (int nt = 0; nt < 8; nt++)
            #pragma unroll
            for (int i = 0; i < 4; i++) acc[mt][nt][i] = 0.0f;

    const uint32_t* Ap = A  + (size_t)bm * KW;
    const uint32_t* Bp = Bw + (size_t)bn * KW;

    auto load_stage = [&](int stage, int c) {
        const uint32_t ab = sb + stage * STAGE_B;
        const uint32_t bb = ab + ATILE_B;
        #pragma unroll
        for (int p = 0; p < 2; p++) {
            const int row = lrow + p * 64;
            cp_async16(ab + (uint32_t)(row * 64 + ltb * 16),
                       Ap + (size_t)row * KW + c * 16 + ltb * 4);
            cp_async16(bb + (uint32_t)(row * 64 + ltb * 16),
                       Bp + (size_t)row * KW + c * 16 + ltb * 4);
        }
    };

    load_stage(0, 0);
    asm volatile("cp.async.commit_group;" ::: "memory");
    load_stage(1, 1);
    asm volatile("cp.async.commit_group;" ::: "memory");

    int buf = 0;
    for (int c = 0; c < NC; c++) {
        asm volatile("cp.async.wait_group 1;" ::: "memory");
        __syncthreads();

        if (c + 2 < NC) load_stage((buf + 2) % NSTG, c + 2);
        asm volatile("cp.async.commit_group;" ::: "memory");

        const uint32_t* sA = sm + buf * (STAGE_B / 4);
        const uint32_t* sB = sA + (ATILE_B / 4);

        // A fragments: one LDS.128 per row-half per mt covers the whole K32
        uint4 af[2][2];
        #pragma unroll
        for (int mt = 0; mt < 2; mt++) {
            const uint32_t* pa = sA + (wm + mt * 16 + g) * 16 + t * 4;
            af[mt][0] = *reinterpret_cast<const uint4*>(pa);
            af[mt][1] = *reinterpret_cast<const uint4*>(pa + 8 * 16);
        }
        // B in two halves of 4 nt to bound register pressure
        #pragma unroll
        for (int nh = 0; nh < 2; nh++) {
            uint4 bf[4];
            #pragma unroll
            for (int j = 0; j < 4; j++)
                bf[j] = *reinterpret_cast<const uint4*>(
                    sB + (wn + nh * 32 + j * 8 + g) * 16 + t * 4);
            #pragma unroll
            for (int mt = 0; mt < 2; mt++)
                #pragma unroll
                for (int j = 0; j < 4; j++) {
                    float* a = acc[mt][nh * 4 + j];
                    mma_f16(a, af[mt][0].x, af[mt][1].x, af[mt][0].y, af[mt][1].y,
                            bf[j].x, bf[j].y);
                    mma_f16(a, af[mt][0].z, af[mt][1].z, af[mt][0].w, af[mt][1].w,
                            bf[j].z, bf[j].w);
                }
        }

        buf = (buf + 1) % NSTG;
    }

    // epilogue
    float*    Cf = (float*)Cout;
    uint32_t* Ch = (uint32_t*)Cout;
    #pragma unroll
    for (int mt = 0; mt < 2; mt++) {
        const int r0 = bm + wm + mt * 16 + g;
        #pragma unroll
        for (int nt = 0; nt < 8; nt++) {
            const int cc = bn + wn + nt * 8 + 2 * t;
            const float2 bv = *reinterpret_cast<const float2*>(bias + cc);
            float v00 = acc[mt][nt][0] + bv.x;
            float v01 = acc[mt][nt][1] + bv.y;
            float v10 = acc[mt][nt][2] + bv.x;
            float v11 = acc[mt][nt][3] + bv.y;
            if (MODE == 1) {
                v00 = fmaxf(v00, 0.0f); v01 = fmaxf(v01, 0.0f);
                v10 = fmaxf(v10, 0.0f); v11 = fmaxf(v11, 0.0f);
                const int u = hperm_u32(cc & 31) + (cc >> 5) * 16;
                Ch[(size_t)r0 * (N >> 1) + u]       = h2u(v00, v01);
                Ch[(size_t)(r0 + 8) * (N >> 1) + u] = h2u(v10, v11);
            } else {
                *reinterpret_cast<float2*>(Cf + (size_t)r0 * N + cc)
                    = make_float2(v00, v01);
                *reinterpret_cast<float2*>(Cf + (size_t)(r0 + 8) * N + cc)
                    = make_float2(v10, v11);
            }
        }
    }
}

// ---------------- fused cvt: all 6 operands in ONE launch -------------------
// Every segment's float4 count is a multiple of 256, so each block maps to
// exactly one segment (no divergence). Per float4: two permuted half2 stores.
__device__ __forceinline__ void cvt_one(const float4* __restrict__ src,
                                        uint32_t* __restrict__ dst, int f) {
    const float4 v = src[f];
    const int k0  = (f * 4) & 31;
    const int blk = f >> 3;
    dst[blk * 16 + hperm_u32(k0)]     = h2u(v.x, v.y);
    dst[blk * 16 + hperm_u32(k0 + 2)] = h2u(v.z, v.w);
}

__global__ void cvt_all_kernel(const float4* s0, uint32_t* d0, int c0,
                               const float4* s1, uint32_t* d1, int c1,
                               const float4* s2, uint32_t* d2, int c2,
                               const float4* s3, uint32_t* d3, int c3,
                               const float4* s4, uint32_t* d4, int c4,
                               const float4* s5, uint32_t* d5) {
    const int f = blockIdx.x * 256 + threadIdx.x;
    if      (f < c0) cvt_one(s0, d0, f);
    else if (f < c1) cvt_one(s1, d1, f - c0);
    else if (f < c2) cvt_one(s2, d2, f - c1);
    else if (f < c3) cvt_one(s3, d3, f - c2);
    else if (f < c4) cvt_one(s4, d4, f - c3);
    else             cvt_one(s5, d5, f - c4);
}

// ---------------- GRU elementwise ------------------------------------------
__global__ void gru_kernel(const float4* __restrict__ hin,
                           float4* __restrict__ hout,
                           uint32_t* __restrict__ hc) {
    const int idx = blockIdx.x * 256 + threadIdx.x;      // over B*H/4
    const int b = idx >> 9;                              // H/4 = 512
    const int i = idx & 511;
    const float4* gi = reinterpret_cast<const float4*>(g_gi) + (size_t)b * (3 * H_DIM / 4);
    const float4* gh = reinterpret_cast<const float4*>(g_gh) + (size_t)b * (3 * H_DIM / 4);
    const float4 ir = gi[i], iz = gi[512 + i], inn = gi[1024 + i];
    const float4 hr = gh[i], hz = gh[512 + i], hn  = gh[1024 + i];
    const float4 h0 = hin[idx];
    float4 o;
    {
        float r = 1.0f / (1.0f + expf(-(ir.x + hr.x)));
        float z = 1.0f / (1.0f + expf(-(iz.x + hz.x)));
        float n = tanhf(inn.x + r * hn.x);
        o.x = (1.0f - z) * n + z * h0.x;
    }
    {
        float r = 1.0f / (1.0f + expf(-(ir.y + hr.y)));
        float z = 1.0f / (1.0f + expf(-(iz.y + hz.y)));
        float n = tanhf(inn.y + r * hn.y);
        o.y = (1.0f - z) * n + z * h0.y;
    }
    {
        float r = 1.0f / (1.0f + expf(-(ir.z + hr.z)));
        float z = 1.0f / (1.0f + expf(-(iz.z + hz.z)));
        float n = tanhf(inn.z + r * hn.z);
        o.z = (1.0f - z) * n + z * h0.z;
    }
    {
        float r = 1.0f / (1.0f + expf(-(ir.w + hr.w)));
        float z = 1.0f / (1.0f + expf(-(iz.w + hz.w)));
        float n = tanhf(inn.w + r * hn.w);
        o.w = (1.0f - z) * n + z * h0.w;
    }
    hout[idx] = o;
    const int e0  = idx * 4;
    const int kk  = e0 & 31;
    const int blk = e0 >> 5;
    hc[blk * 16 + hperm_u32(kk)]     = h2u(o.x, o.y);
    hc[blk * 16 + hperm_u32(kk + 2)] = h2u(o.z, o.w);
}

// ---------------- decode ----------------------------------------------------
// One row per block, 256 threads: 2 threads per output (128 outputs), each
// takes 32 of the 64 window elements with 4 independent max chains, combined
// via shfl_xor. q1[j] = max q[j..j+63]; q2[j] = max_k q[(j+64k-1) & 4095].
__global__ void decode_kernel(float* __restrict__ out) {
    __shared__ float s[A2_DIM];
    const int b = blockIdx.x;
    const float4* qr = reinterpret_cast<const float4*>(g_q + (size_t)b * A2_DIM);
    float4* s4 = reinterpret_cast<float4*>(s);
    #pragma unroll
    for (int i = 0; i < A2_DIM / 4 / 256; i++)
        s4[threadIdx.x + i * 256] = qr[threadIdx.x + i * 256];
    __syncthreads();

    const int t = threadIdx.x;
    const int p = t >> 1;                 // output 0..127
    const int h = t & 1;                  // half of the 64-elem window
    float m0 = -3.402823466e38f, m1 = m0, m2 = m0, m3 = m0;
    if (p < A_DIM) {
        const int base = p + h * 32;
        #pragma unroll
        for (int k = 0; k < 8; k++) {
            m0 = fmaxf(m0, s[base + k]);
            m1 = fmaxf(m1, s[base + 8 + k]);
            m2 = fmaxf(m2, s[base + 16 + k]);
            m3 = fmaxf(m3, s[base + 24 + k]);
        }
    } else {
        const int j = p - A_DIM;
        const int k0 = h * 32;
        #pragma unroll
        for (int k = 0; k < 8; k++) {
            m0 = fmaxf(m0, s[(j + (k0 + k) * 64 + 4095) & 4095]);
            m1 = fmaxf(m1, s[(j + (k0 + k + 8) * 64 + 4095) & 4095]);
            m2 = fmaxf(m2, s[(j + (k0 + k + 16) * 64 + 4095) & 4095]);
            m3 = fmaxf(m3, s[(j + (k0 + k + 24) * 64 + 4095) & 4095]);
        }
    }
    float m = fmaxf(fmaxf(m0, m1), fmaxf(m2, m3));
    m = fmaxf(m, __shfl_xor_sync(0xFFFFFFFF, m, 1));
    if (h == 0) {
        if (p < A_DIM) out[(size_t)(2 * b) * A_DIM + p] = m;
        else           out[(size_t)(2 * b + 1) * A_DIM + (p - A_DIM)] = m;
    }
}

// ---------------- launch ----------------------------------------------------
extern "C" void kernel_launch(void* const* d_in, const int* in_sizes, int n_in,
                              void* d_out, int out_size) {
    const float* inputs = (const float*)d_in[0];
    const float* hidden = (const float*)d_in[1];
    const float* W1  = (const float*)d_in[2];
    const float* b1  = (const float*)d_in[3];
    const float* Wih = (const float*)d_in[4];
    const float* Whh = (const float*)d_in[5];
    const float* bih = (const float*)d_in[6];
    const float* bhh = (const float*)d_in[7];
    const float* W2  = (const float*)d_in[8];
    const float* b2  = (const float*)d_in[9];
    float* out = (float*)d_out;
    float* hout = out + (size_t)2 * B_DIM * A_DIM;   // h region of output

    void *pinc, *phinc, *pW1c, *pWihc, *pWhhc, *pW2c, *px, *pgi, *pgh, *phc, *pq;
    cudaGetSymbolAddress(&pinc,  g_inc);
    cudaGetSymbolAddress(&phinc, g_hinc);
    cudaGetSymbolAddress(&pW1c,  g_W1c);
    cudaGetSymbolAddress(&pWihc, g_Wihc);
    cudaGetSymbolAddress(&pWhhc, g_Whhc);
    cudaGetSymbolAddress(&pW2c,  g_W2c);
    cudaGetSymbolAddress(&px,    g_x);
    cudaGetSymbolAddress(&pgi,   g_gi);
    cudaGetSymbolAddress(&pgh,   g_gh);
    cudaGetSymbolAddress(&phc,   g_hc);
    cudaGetSymbolAddress(&pq,    g_q);

    cudaFuncSetAttribute(gemm_f16k<0>, cudaFuncAttributeMaxDynamicSharedMemorySize, SMEM_BYTES);
    cudaFuncSetAttribute(gemm_f16k<1>, cudaFuncAttributeMaxDynamicSharedMemorySize, SMEM_BYTES);

    // one fused fp32->fp16(+perm) conversion launch for all 6 operands
    {
        const int n0 = B_DIM * IN_DIM / 4;          // 1048576
        const int n1 = B_DIM * H_DIM / 4;           // 2097152
        const int n2 = H_DIM * IN_DIM / 4;          // 524288
        const int n3 = 3 * H_DIM * H_DIM / 4;       // 3145728
        const int n4 = n3;
        const int n5 = A2_DIM * H_DIM / 4;          // 2097152
        const int c0 = n0, c1 = c0 + n1, c2 = c1 + n2,
                  c3 = c2 + n3, c4 = c3 + n4, c5 = c4 + n5;
        cvt_all_kernel<<<c5 / 256, 256>>>(
            (const float4*)inputs, (uint32_t*)pinc,  c0,
            (const float4*)hidden, (uint32_t*)phinc, c1,
            (const float4*)W1,     (uint32_t*)pW1c,  c2,
            (const float4*)Wih,    (uint32_t*)pWihc, c3,
            (const float4*)Whh,    (uint32_t*)pWhhc, c4,
            (const float4*)W2,     (uint32_t*)pW2c);
    }

    const dim3 blk(256);

    // fc1 + relu (+fp16 perm): x = relu(inputs @ W1^T + b1)
    gemm_f16k<1><<<dim3(H_DIM / 128, B_DIM / 128, 1), blk, SMEM_BYTES>>>(
        (const uint32_t*)pinc, (const uint32_t*)pW1c, b1, px,
        (const uint32_t*)pinc, (const uint32_t*)pW1c, b1, px,
        IN_DIM, H_DIM);

    // gi = x @ Wih^T + bih  AND  gh = h_in @ Whh^T + bhh in ONE launch
    gemm_f16k<0><<<dim3(3 * H_DIM / 128, B_DIM / 128, 2), blk, SMEM_BYTES>>>(
        (const uint32_t*)px,    (const uint32_t*)pWihc, bih, pgi,
        (const uint32_t*)phinc, (const uint32_t*)pWhhc, bhh, pgh,
        H_DIM, 3 * H_DIM);

    // GRU elementwise -> exact h into d_out, fp16 permuted h into scratch
    gru_kernel<<<(B_DIM * H_DIM / 4) / 256, 256>>>(
        (const float4*)hidden, (float4*)hout, (uint32_t*)phc);

    // fc2: q = h @ W2^T + b2
    gemm_f16k<0><<<dim3(A2_DIM / 128, B_DIM / 128, 1), blk, SMEM_BYTES>>>(
        (const uint32_t*)phc, (const uint32_t*)pW2c, b2, pq,
        (const uint32_t*)phc, (const uint32_t*)pW2c, b2, pq,
        H_DIM, A2_DIM);

    // decode -> d_out[0 .. 2B*A)
    decode_kernel<<<B_DIM, 256>>>(out);
}

// round 14
// speedup vs baseline: 1.4632x; 1.4632x over previous
#include <cuda_runtime.h>
#include <cuda_fp16.h>
#include <math.h>
#include <stdint.h>

#define B_DIM 4096
#define IN_DIM 1024
#define H_DIM 2048
#define A_DIM 64
#define A2_DIM 4096

// ---------------- scratch (__device__ globals; no allocs allowed) ----------
// GEMM operands stored as fp16 pairs (uint32 = half2), k-PERMUTED:
// within each 32-k block, element k lives at pos = 8*((k&7)>>1) + 2*(k>>3) + (k&1).
__device__ uint32_t g_inc [B_DIM * IN_DIM / 2];
__device__ uint32_t g_hinc[B_DIM * H_DIM / 2];
__device__ uint32_t g_W1c [H_DIM * IN_DIM / 2];
__device__ uint32_t g_Wihc[3 * H_DIM * H_DIM / 2];
__device__ uint32_t g_Whhc[3 * H_DIM * H_DIM / 2];
__device__ uint32_t g_W2c [A2_DIM * H_DIM / 2];
__device__ uint32_t g_x   [B_DIM * H_DIM / 2];      // fc1 out (relu, fp16, perm)
__device__ float    g_gi  [B_DIM * 3 * H_DIM];      // fp32 plain
__device__ float    g_gh  [B_DIM * 3 * H_DIM];      // fp32 plain
__device__ uint32_t g_hc  [B_DIM * H_DIM / 2];      // new hidden (fp16, perm)
__device__ float    g_q   [B_DIM * A2_DIM];         // fp32 plain

// ---------------- helpers --------------------------------------------------
__device__ __forceinline__ uint32_t smem_u32(const void* p) {
    uint32_t a;
    asm("{ .reg .u64 t; cvta.to.shared.u64 t, %1; cvt.u32.u64 %0, t; }"
        : "=r"(a) : "l"(p));
    return a;
}
__device__ __forceinline__ uint32_t h2u(float a, float b) {
    __half2 h = __floats2half2_rn(a, b);     // low = a (even k), high = b
    return *reinterpret_cast<uint32_t*>(&h);
}
__device__ __forceinline__ void cp_async16(uint32_t dst, const void* src) {
    asm volatile("cp.async.cg.shared.global [%0], [%1], 16;" :: "r"(dst), "l"(src));
}
__device__ __forceinline__ void mma_f16(float* c,
                                        uint32_t a0, uint32_t a1, uint32_t a2, uint32_t a3,
                                        uint32_t b0, uint32_t b1) {
    asm volatile(
        "mma.sync.aligned.m16n8k16.row.col.f32.f16.f16.f32 "
        "{%0,%1,%2,%3}, {%4,%5,%6,%7}, {%8,%9}, {%0,%1,%2,%3};"
        : "+f"(c[0]), "+f"(c[1]), "+f"(c[2]), "+f"(c[3])
        : "r"(a0), "r"(a1), "r"(a2), "r"(a3), "r"(b0), "r"(b1));
}
// uint32 index (within a row of N/2 uint32) of the half2 holding (k, k+1), k even
__device__ __forceinline__ int hperm_u32(int k) {
    return (k >> 5) * 16 + ((k & 7) >> 1) * 4 + ((k & 31) >> 3);
}

// ---------------- fp16 mma.sync GEMM (round-12 exact) -----------------------
// C[M,N] = A[M,K] @ Bw[N,K]^T + bias. CTA 128x128, BK=32, 256 thr, occ 2,
// 3-stage cp.async ring, one barrier per chunk. SINGLE problem per launch
// (the dual-pointer blockIdx.z variant regressed all GEMMs via reg pressure).
#define ATILE_B 8192                      // 128 rows x 64 B
#define STAGE_B (2 * ATILE_B)             // A + B
#define NSTG 3
#define SMEM_BYTES (NSTG * STAGE_B)       // 49152 B

template<int MODE>   // 0: fp32 plain store; 1: relu + fp16 PERMUTED store
__global__ __launch_bounds__(256, 2)
void gemm_f16k(const uint32_t* __restrict__ A, const uint32_t* __restrict__ Bw,
               const float* __restrict__ bias, void* __restrict__ Cout,
               int K, int N) {
    extern __shared__ uint32_t sm[];
    const int tid  = threadIdx.x;
    const int bm   = blockIdx.y * 128;
    const int bn   = blockIdx.x * 128;
    const int warp = tid >> 5, lane = tid & 31;
    const int wm   = (warp & 3) * 32;
    const int wn   = (warp >> 2) * 64;
    const int g    = lane >> 2;           // row-in-8 group
    const int t    = lane & 3;            // k phase
    const int NC   = K >> 5;              // K chunks of 32
    const int KW   = K >> 1;              // uint32 per operand row

    const uint32_t sb = smem_u32(sm);
    const int lrow = tid >> 2;            // loader row 0..63 (+64)
    const int ltb  = tid & 3;             // 16B block within 64B row-chunk

    float acc[2][8][4];
    #pragma unroll
    for (int mt = 0; mt < 2; mt++)
        #pragma unroll
        for (int nt = 0; nt < 8; nt++)
            #pragma unroll
            for (int i = 0; i < 4; i++) acc[mt][nt][i] = 0.0f;

    const uint32_t* Ap = A  + (size_t)bm * KW;
    const uint32_t* Bp = Bw + (size_t)bn * KW;

    auto load_stage = [&](int stage, int c) {
        const uint32_t ab = sb + stage * STAGE_B;
        const uint32_t bb = ab + ATILE_B;
        #pragma unroll
        for (int p = 0; p < 2; p++) {
            const int row = lrow + p * 64;
            cp_async16(ab + (uint32_t)(row * 64 + ltb * 16),
                       Ap + (size_t)row * KW + c * 16 + ltb * 4);
            cp_async16(bb + (uint32_t)(row * 64 + ltb * 16),
                       Bp + (size_t)row * KW + c * 16 + ltb * 4);
        }
    };

    load_stage(0, 0);
    asm volatile("cp.async.commit_group;" ::: "memory");
    load_stage(1, 1);
    asm volatile("cp.async.commit_group;" ::: "memory");

    int buf = 0;
    for (int c = 0; c < NC; c++) {
        asm volatile("cp.async.wait_group 1;" ::: "memory");
        __syncthreads();

        if (c + 2 < NC) load_stage((buf + 2) % NSTG, c + 2);
        asm volatile("cp.async.commit_group;" ::: "memory");

        const uint32_t* sA = sm + buf * (STAGE_B / 4);
        const uint32_t* sB = sA + (ATILE_B / 4);

        // A fragments: one LDS.128 per row-half per mt covers the whole K32
        uint4 af[2][2];
        #pragma unroll
        for (int mt = 0; mt < 2; mt++) {
            const uint32_t* pa = sA + (wm + mt * 16 + g) * 16 + t * 4;
            af[mt][0] = *reinterpret_cast<const uint4*>(pa);
            af[mt][1] = *reinterpret_cast<const uint4*>(pa + 8 * 16);
        }
        // B in two halves of 4 nt to bound register pressure
        #pragma unroll
        for (int nh = 0; nh < 2; nh++) {
            uint4 bf[4];
            #pragma unroll
            for (int j = 0; j < 4; j++)
                bf[j] = *reinterpret_cast<const uint4*>(
                    sB + (wn + nh * 32 + j * 8 + g) * 16 + t * 4);
            #pragma unroll
            for (int mt = 0; mt < 2; mt++)
                #pragma unroll
                for (int j = 0; j < 4; j++) {
                    float* a = acc[mt][nh * 4 + j];
                    mma_f16(a, af[mt][0].x, af[mt][1].x, af[mt][0].y, af[mt][1].y,
                            bf[j].x, bf[j].y);
                    mma_f16(a, af[mt][0].z, af[mt][1].z, af[mt][0].w, af[mt][1].w,
                            bf[j].z, bf[j].w);
                }
        }

        buf = (buf + 1) % NSTG;
    }

    // epilogue
    float*    Cf = (float*)Cout;
    uint32_t* Ch = (uint32_t*)Cout;
    #pragma unroll
    for (int mt = 0; mt < 2; mt++) {
        const int r0 = bm + wm + mt * 16 + g;
        #pragma unroll
        for (int nt = 0; nt < 8; nt++) {
            const int cc = bn + wn + nt * 8 + 2 * t;
            const float2 bv = *reinterpret_cast<const float2*>(bias + cc);
            float v00 = acc[mt][nt][0] + bv.x;
            float v01 = acc[mt][nt][1] + bv.y;
            float v10 = acc[mt][nt][2] + bv.x;
            float v11 = acc[mt][nt][3] + bv.y;
            if (MODE == 1) {
                v00 = fmaxf(v00, 0.0f); v01 = fmaxf(v01, 0.0f);
                v10 = fmaxf(v10, 0.0f); v11 = fmaxf(v11, 0.0f);
                const int u = hperm_u32(cc & 31) + (cc >> 5) * 16;
                Ch[(size_t)r0 * (N >> 1) + u]       = h2u(v00, v01);
                Ch[(size_t)(r0 + 8) * (N >> 1) + u] = h2u(v10, v11);
            } else {
                *reinterpret_cast<float2*>(Cf + (size_t)r0 * N + cc)
                    = make_float2(v00, v01);
                *reinterpret_cast<float2*>(Cf + (size_t)(r0 + 8) * N + cc)
                    = make_float2(v10, v11);
            }
        }
    }
}

// ---------------- fused cvt: all 6 operands in ONE launch -------------------
__device__ __forceinline__ void cvt_one(const float4* __restrict__ src,
                                        uint32_t* __restrict__ dst, int f) {
    const float4 v = src[f];
    const int k0  = (f * 4) & 31;
    const int blk = f >> 3;
    dst[blk * 16 + hperm_u32(k0)]     = h2u(v.x, v.y);
    dst[blk * 16 + hperm_u32(k0 + 2)] = h2u(v.z, v.w);
}

__global__ void cvt_all_kernel(const float4* s0, uint32_t* d0, int c0,
                               const float4* s1, uint32_t* d1, int c1,
                               const float4* s2, uint32_t* d2, int c2,
                               const float4* s3, uint32_t* d3, int c3,
                               const float4* s4, uint32_t* d4, int c4,
                               const float4* s5, uint32_t* d5) {
    const int f = blockIdx.x * 256 + threadIdx.x;
    if      (f < c0) cvt_one(s0, d0, f);
    else if (f < c1) cvt_one(s1, d1, f - c0);
    else if (f < c2) cvt_one(s2, d2, f - c1);
    else if (f < c3) cvt_one(s3, d3, f - c2);
    else if (f < c4) cvt_one(s4, d4, f - c3);
    else             cvt_one(s5, d5, f - c4);
}

// ---------------- GRU elementwise ------------------------------------------
__global__ void gru_kernel(const float4* __restrict__ hin,
                           float4* __restrict__ hout,
                           uint32_t* __restrict__ hc) {
    const int idx = blockIdx.x * 256 + threadIdx.x;      // over B*H/4
    const int b = idx >> 9;                              // H/4 = 512
    const int i = idx & 511;
    const float4* gi = reinterpret_cast<const float4*>(g_gi) + (size_t)b * (3 * H_DIM / 4);
    const float4* gh = reinterpret_cast<const float4*>(g_gh) + (size_t)b * (3 * H_DIM / 4);
    const float4 ir = gi[i], iz = gi[512 + i], inn = gi[1024 + i];
    const float4 hr = gh[i], hz = gh[512 + i], hn  = gh[1024 + i];
    const float4 h0 = hin[idx];
    float4 o;
    {
        float r = 1.0f / (1.0f + expf(-(ir.x + hr.x)));
        float z = 1.0f / (1.0f + expf(-(iz.x + hz.x)));
        float n = tanhf(inn.x + r * hn.x);
        o.x = (1.0f - z) * n + z * h0.x;
    }
    {
        float r = 1.0f / (1.0f + expf(-(ir.y + hr.y)));
        float z = 1.0f / (1.0f + expf(-(iz.y + hz.y)));
        float n = tanhf(inn.y + r * hn.y);
        o.y = (1.0f - z) * n + z * h0.y;
    }
    {
        float r = 1.0f / (1.0f + expf(-(ir.z + hr.z)));
        float z = 1.0f / (1.0f + expf(-(iz.z + hz.z)));
        float n = tanhf(inn.z + r * hn.z);
        o.z = (1.0f - z) * n + z * h0.z;
    }
    {
        float r = 1.0f / (1.0f + expf(-(ir.w + hr.w)));
        float z = 1.0f / (1.0f + expf(-(iz.w + hz.w)));
        float n = tanhf(inn.w + r * hn.w);
        o.w = (1.0f - z) * n + z * h0.w;
    }
    hout[idx] = o;
    const int e0  = idx * 4;
    const int kk  = e0 & 31;
    const int blk = e0 >> 5;
    hc[blk * 16 + hperm_u32(kk)]     = h2u(o.x, o.y);
    hc[blk * 16 + hperm_u32(kk + 2)] = h2u(o.z, o.w);
}

// ---------------- decode ----------------------------------------------------
// One row per block, 256 threads: 2 threads per output (128 outputs), each
// takes 32 of the 64 window elements with 4 independent max chains, combined
// via shfl_xor. q1[j] = max q[j..j+63]; q2[j] = max_k q[(j+64k-1) & 4095].
__global__ void decode_kernel(float* __restrict__ out) {
    __shared__ float s[A2_DIM];
    const int b = blockIdx.x;
    const float4* qr = reinterpret_cast<const float4*>(g_q + (size_t)b * A2_DIM);
    float4* s4 = reinterpret_cast<float4*>(s);
    #pragma unroll
    for (int i = 0; i < A2_DIM / 4 / 256; i++)
        s4[threadIdx.x + i * 256] = qr[threadIdx.x + i * 256];
    __syncthreads();

    const int t = threadIdx.x;
    const int p = t >> 1;                 // output 0..127
    const int h = t & 1;                  // half of the 64-elem window
    float m0 = -3.402823466e38f, m1 = m0, m2 = m0, m3 = m0;
    if (p < A_DIM) {
        const int base = p + h * 32;
        #pragma unroll
        for (int k = 0; k < 8; k++) {
            m0 = fmaxf(m0, s[base + k]);
            m1 = fmaxf(m1, s[base + 8 + k]);
            m2 = fmaxf(m2, s[base + 16 + k]);
            m3 = fmaxf(m3, s[base + 24 + k]);
        }
    } else {
        const int j = p - A_DIM;
        const int k0 = h * 32;
        #pragma unroll
        for (int k = 0; k < 8; k++) {
            m0 = fmaxf(m0, s[(j + (k0 + k) * 64 + 4095) & 4095]);
            m1 = fmaxf(m1, s[(j + (k0 + k + 8) * 64 + 4095) & 4095]);
            m2 = fmaxf(m2, s[(j + (k0 + k + 16) * 64 + 4095) & 4095]);
            m3 = fmaxf(m3, s[(j + (k0 + k + 24) * 64 + 4095) & 4095]);
        }
    }
    float m = fmaxf(fmaxf(m0, m1), fmaxf(m2, m3));
    m = fmaxf(m, __shfl_xor_sync(0xFFFFFFFF, m, 1));
    if (h == 0) {
        if (p < A_DIM) out[(size_t)(2 * b) * A_DIM + p] = m;
        else           out[(size_t)(2 * b + 1) * A_DIM + (p - A_DIM)] = m;
    }
}

// ---------------- launch ----------------------------------------------------
extern "C" void kernel_launch(void* const* d_in, const int* in_sizes, int n_in,
                              void* d_out, int out_size) {
    const float* inputs = (const float*)d_in[0];
    const float* hidden = (const float*)d_in[1];
    const float* W1  = (const float*)d_in[2];
    const float* b1  = (const float*)d_in[3];
    const float* Wih = (const float*)d_in[4];
    const float* Whh = (const float*)d_in[5];
    const float* bih = (const float*)d_in[6];
    const float* bhh = (const float*)d_in[7];
    const float* W2  = (const float*)d_in[8];
    const float* b2  = (const float*)d_in[9];
    float* out = (float*)d_out;
    float* hout = out + (size_t)2 * B_DIM * A_DIM;   // h region of output

    void *pinc, *phinc, *pW1c, *pWihc, *pWhhc, *pW2c, *px, *pgi, *pgh, *phc, *pq;
    cudaGetSymbolAddress(&pinc,  g_inc);
    cudaGetSymbolAddress(&phinc, g_hinc);
    cudaGetSymbolAddress(&pW1c,  g_W1c);
    cudaGetSymbolAddress(&pWihc, g_Wihc);
    cudaGetSymbolAddress(&pWhhc, g_Whhc);
    cudaGetSymbolAddress(&pW2c,  g_W2c);
    cudaGetSymbolAddress(&px,    g_x);
    cudaGetSymbolAddress(&pgi,   g_gi);
    cudaGetSymbolAddress(&pgh,   g_gh);
    cudaGetSymbolAddress(&phc,   g_hc);
    cudaGetSymbolAddress(&pq,    g_q);

    cudaFuncSetAttribute(gemm_f16k<0>, cudaFuncAttributeMaxDynamicSharedMemorySize, SMEM_BYTES);
    cudaFuncSetAttribute(gemm_f16k<1>, cudaFuncAttributeMaxDynamicSharedMemorySize, SMEM_BYTES);

    // one fused fp32->fp16(+perm) conversion launch for all 6 operands
    {
        const int n0 = B_DIM * IN_DIM / 4;          // 1048576
        const int n1 = B_DIM * H_DIM / 4;           // 2097152
        const int n2 = H_DIM * IN_DIM / 4;          // 524288
        const int n3 = 3 * H_DIM * H_DIM / 4;       // 3145728
        const int n4 = n3;
        const int n5 = A2_DIM * H_DIM / 4;          // 2097152
        const int c0 = n0, c1 = c0 + n1, c2 = c1 + n2,
                  c3 = c2 + n3, c4 = c3 + n4, c5 = c4 + n5;
        cvt_all_kernel<<<c5 / 256, 256>>>(
            (const float4*)inputs, (uint32_t*)pinc,  c0,
            (const float4*)hidden, (uint32_t*)phinc, c1,
            (const float4*)W1,     (uint32_t*)pW1c,  c2,
            (const float4*)Wih,    (uint32_t*)pWihc, c3,
            (const float4*)Whh,    (uint32_t*)pWhhc, c4,
            (const float4*)W2,     (uint32_t*)pW2c);
    }

    const dim3 blk(256);

    // fc1 + relu (+fp16 perm): x = relu(inputs @ W1^T + b1)
    gemm_f16k<1><<<dim3(H_DIM / 128, B_DIM / 128), blk, SMEM_BYTES>>>(
        (const uint32_t*)pinc, (const uint32_t*)pW1c, b1, px, IN_DIM, H_DIM);

    // gi = x @ Wih^T + bih ; gh = h_in @ Whh^T + bhh (separate launches)
    gemm_f16k<0><<<dim3(3 * H_DIM / 128, B_DIM / 128), blk, SMEM_BYTES>>>(
        (const uint32_t*)px, (const uint32_t*)pWihc, bih, pgi, H_DIM, 3 * H_DIM);
    gemm_f16k<0><<<dim3(3 * H_DIM / 128, B_DIM / 128), blk, SMEM_BYTES>>>(
        (const uint32_t*)phinc, (const uint32_t*)pWhhc, bhh, pgh, H_DIM, 3 * H_DIM);

    // GRU elementwise -> exact h into d_out, fp16 permuted h into scratch
    gru_kernel<<<(B_DIM * H_DIM / 4) / 256, 256>>>(
        (const float4*)hidden, (float4*)hout, (uint32_t*)phc);

    // fc2: q = h @ W2^T + b2
    gemm_f16k<0><<<dim3(A2_DIM / 128, B_DIM / 128), blk, SMEM_BYTES>>>(
        (const uint32_t*)phc, (const uint32_t*)pW2c, b2, pq, H_DIM, A2_DIM);

    // decode -> d_out[0 .. 2B*A)
    decode_kernel<<<B_DIM, 256>>>(out);
}